// round 2
// baseline (speedup 1.0000x reference)
#include <cuda_runtime.h>
#include <cuda_bf16.h>

// Conv2D 4096x4096, 15x15 kernel, pad=1, stride=1 -> out 4084x4084, + bias.
// Tiled direct convolution, 128x32 output tile per 256-thread block,
// 4x4 register blocking, input halo staged in shared memory.

#define KS      15
#define IN_N    4096
#define OUT_N   4084        // 4096 + 2*1 - 15 + 1
#define TS_X    128
#define TS_Y    32
#define RX      4
#define RY      4
#define BDX     32
#define BDY     8
#define SMW     (TS_X + KS - 1)   // 142
#define SMW_PAD 144               // 16B-aligned rows, keeps float4 LDS aligned
#define SMH     (TS_Y + KS - 1)   // 46

__global__ __launch_bounds__(BDX * BDY)
void conv2d_15x15_kernel(const float* __restrict__ x,
                         const float* __restrict__ w,
                         const float* __restrict__ bias,
                         float* __restrict__ out)
{
    __shared__ float sX[SMH][SMW_PAD];
    __shared__ float sW[KS * KS + 1];

    const int tx  = threadIdx.x;
    const int ty  = threadIdx.y;
    const int tid = ty * BDX + tx;
    const int bx  = blockIdx.x * TS_X;
    const int by  = blockIdx.y * TS_Y;

    // ---- stage weights ----
    if (tid < KS * KS) sW[tid] = w[tid];

    // ---- stage input halo tile (zero-padded at borders) ----
    #pragma unroll
    for (int r = ty; r < SMH; r += BDY) {
        const int gy = by + r - 1;                       // pad = 1
        const bool rowok = (gy >= 0) && (gy < IN_N);
        const float* xrow = x + (size_t)gy * IN_N;
        for (int c = tx; c < SMW; c += BDX) {
            const int gx = bx + c - 1;
            float v = 0.0f;
            if (rowok && gx >= 0 && gx < IN_N) v = xrow[gx];
            sX[r][c] = v;
        }
        // pad columns [SMW, SMW_PAD) so the float4 reads below never see NaNs
        if (tx < SMW_PAD - SMW) sX[r][SMW + tx] = 0.0f;
    }
    __syncthreads();

    // ---- compute 4x4 outputs per thread ----
    float acc[RY][RX];
    #pragma unroll
    for (int i = 0; i < RY; ++i)
        #pragma unroll
        for (int j = 0; j < RX; ++j)
            acc[i][j] = 0.0f;

    const int cx = tx * RX;   // local output col base
    const int cy = ty * RY;   // local output row base

    for (int dy = 0; dy < KS; ++dy) {          // NOT unrolled: keep body in L0 I$
        float wr[KS];
        #pragma unroll
        for (int k = 0; k < KS; ++k) wr[k] = sW[dy * KS + k];   // LDS broadcast

        #pragma unroll
        for (int i = 0; i < RY; ++i) {
            // registers: 20 floats covering cols [cx, cx+19]; need [cx, cx+17]
            const float4* p = reinterpret_cast<const float4*>(&sX[cy + i + dy][cx]);
            float xr[RX + 16];
            float4 v0 = p[0], v1 = p[1], v2 = p[2], v3 = p[3], v4 = p[4];
            xr[0]=v0.x;  xr[1]=v0.y;  xr[2]=v0.z;  xr[3]=v0.w;
            xr[4]=v1.x;  xr[5]=v1.y;  xr[6]=v1.z;  xr[7]=v1.w;
            xr[8]=v2.x;  xr[9]=v2.y;  xr[10]=v2.z; xr[11]=v2.w;
            xr[12]=v3.x; xr[13]=v3.y; xr[14]=v3.z; xr[15]=v3.w;
            xr[16]=v4.x; xr[17]=v4.y; xr[18]=v4.z; xr[19]=v4.w;

            #pragma unroll
            for (int dx = 0; dx < KS; ++dx) {
                const float wv = wr[dx];
                #pragma unroll
                for (int j = 0; j < RX; ++j)
                    acc[i][j] = fmaf(wv, xr[j + dx], acc[i][j]);
            }
        }
    }

    // ---- store (float4, fully coalesced; 4084 % 4 == 0) ----
    const float b = bias[0];
    const int ox  = bx + cx;
    const int oy0 = by + cy;
    if (ox < OUT_N) {
        #pragma unroll
        for (int i = 0; i < RY; ++i) {
            const int oy = oy0 + i;
            if (oy < OUT_N) {
                float4 r;
                r.x = acc[i][0] + b;
                r.y = acc[i][1] + b;
                r.z = acc[i][2] + b;
                r.w = acc[i][3] + b;
                *reinterpret_cast<float4*>(&out[(size_t)oy * OUT_N + ox]) = r;
            }
        }
    }
}

extern "C" void kernel_launch(void* const* d_in, const int* in_sizes, int n_in,
                              void* d_out, int out_size)
{
    const float* x    = (const float*)d_in[0];   // 4096*4096
    const float* w    = (const float*)d_in[1];   // 15*15
    const float* bias = (const float*)d_in[2];   // 1
    float* out        = (float*)d_out;           // 4084*4084

    dim3 block(BDX, BDY);
    dim3 grid((OUT_N + TS_X - 1) / TS_X,         // 32
              (OUT_N + TS_Y - 1) / TS_Y);        // 128
    conv2d_15x15_kernel<<<grid, block>>>(x, w, bias, out);
}

// round 3
// speedup vs baseline: 1.0818x; 1.0818x over previous
#include <cuda_runtime.h>
#include <cuda_bf16.h>

// Conv2D 4096x4096, 15x15, pad=1, stride=1 -> 4084x4084, + bias.
// R3: diagonal (r = i+dy) restructure for 4x row-reuse of LDS windows,
// weights in __constant__ (LDCU/uniform path, zero L1 traffic).

#define KS      15
#define IN_N    4096
#define OUT_N   4084
#define TS_X    128
#define TS_Y    32
#define RX      4
#define RY      4
#define BDX     32
#define BDY     8
#define SMW     (TS_X + KS - 1)   // 142
#define SMW_PAD 144               // 16B-aligned rows
#define SMH     (TS_Y + KS - 1)   // 46
#define NR      (RY + KS - 1)     // 18 distinct input rows per thread

__constant__ float cW[KS * KS];

__global__ __launch_bounds__(BDX * BDY)
void conv2d_15x15_kernel(const float* __restrict__ x,
                         const float* __restrict__ bias,
                         float* __restrict__ out)
{
    __shared__ float sX[SMH][SMW_PAD];

    const int tx  = threadIdx.x;
    const int ty  = threadIdx.y;
    const int bx  = blockIdx.x * TS_X;
    const int by  = blockIdx.y * TS_Y;

    // ---- stage input halo tile (zero-padded at borders) ----
    #pragma unroll
    for (int r = ty; r < SMH; r += BDY) {
        const int gy = by + r - 1;                       // pad = 1
        const bool rowok = (gy >= 0) && (gy < IN_N);
        const float* xrow = x + (size_t)gy * IN_N;
        for (int c = tx; c < SMW; c += BDX) {
            const int gx = bx + c - 1;
            float v = 0.0f;
            if (rowok && gx >= 0 && gx < IN_N) v = xrow[gx];
            sX[r][c] = v;
        }
        if (tx < SMW_PAD - SMW) sX[r][SMW + tx] = 0.0f;  // pad cols for float4
    }
    __syncthreads();

    float acc[RY][RX];
    #pragma unroll
    for (int i = 0; i < RY; ++i)
        #pragma unroll
        for (int j = 0; j < RX; ++j)
            acc[i][j] = 0.0f;

    const int cx = tx * RX;   // local output col base (16B-aligned LDS.128)
    const int cy = ty * RY;   // local output row base

    // ---- diagonal loop: each input row loaded ONCE, used by all (i, dy=r-i) ----
    #pragma unroll
    for (int r = 0; r < NR; ++r) {
        // 20-float register window of row cy+r: 5x conflict-free LDS.128
        const float4* p = reinterpret_cast<const float4*>(&sX[cy + r][cx]);
        float xr[RX + 16];
        {
            float4 v0 = p[0], v1 = p[1], v2 = p[2], v3 = p[3], v4 = p[4];
            xr[0]=v0.x;  xr[1]=v0.y;  xr[2]=v0.z;  xr[3]=v0.w;
            xr[4]=v1.x;  xr[5]=v1.y;  xr[6]=v1.z;  xr[7]=v1.w;
            xr[8]=v2.x;  xr[9]=v2.y;  xr[10]=v2.z; xr[11]=v2.w;
            xr[12]=v3.x; xr[13]=v3.y; xr[14]=v3.z; xr[15]=v3.w;
            xr[16]=v4.x; xr[17]=v4.y; xr[18]=v4.z; xr[19]=v4.w;
        }
        #pragma unroll
        for (int i = 0; i < RY; ++i) {
            const int dy = r - i;                 // compile-time after unroll
            if (dy >= 0 && dy < KS) {
                #pragma unroll
                for (int dx = 0; dx < KS; ++dx) {
                    const float wv = cW[dy * KS + dx];   // LDCU -> UR, no L1
                    #pragma unroll
                    for (int j = 0; j < RX; ++j)
                        acc[i][j] = fmaf(wv, xr[j + dx], acc[i][j]);
                }
            }
        }
    }

    // ---- store (float4, coalesced; 4084 % 4 == 0) ----
    const float b = bias[0];
    const int ox  = bx + cx;
    const int oy0 = by + cy;
    if (ox < OUT_N) {
        #pragma unroll
        for (int i = 0; i < RY; ++i) {
            const int oy = oy0 + i;
            if (oy < OUT_N) {
                float4 rr;
                rr.x = acc[i][0] + b;
                rr.y = acc[i][1] + b;
                rr.z = acc[i][2] + b;
                rr.w = acc[i][3] + b;
                *reinterpret_cast<float4*>(&out[(size_t)oy * OUT_N + ox]) = rr;
            }
        }
    }
}

extern "C" void kernel_launch(void* const* d_in, const int* in_sizes, int n_in,
                              void* d_out, int out_size)
{
    const float* x    = (const float*)d_in[0];   // 4096*4096
    const float* w    = (const float*)d_in[1];   // 15*15 (device)
    const float* bias = (const float*)d_in[2];   // 1
    float* out        = (float*)d_out;           // 4084*4084

    // Graph-capturable D2D copy of weights into constant memory (memcpy node).
    cudaMemcpyToSymbolAsync(cW, w, KS * KS * sizeof(float), 0,
                            cudaMemcpyDeviceToDevice, 0);

    dim3 block(BDX, BDY);
    dim3 grid((OUT_N + TS_X - 1) / TS_X,         // 32
              (OUT_N + TS_Y - 1) / TS_Y);        // 128
    conv2d_15x15_kernel<<<grid, block>>>(x, bias, out);
}

// round 4
// speedup vs baseline: 1.1591x; 1.0714x over previous
#include <cuda_runtime.h>

// Conv2D 4096x4096, 15x15, pad=1 -> 4084x4084, + bias.
// R4: packed fp32 (fma.rn.f32x2) — 2 MACs per fma-pipe issue slot.
//   - duplicated (w,w) weight pairs prepped into __constant__, read via LDCU.64
//   - RX=8/RY=2 diagonal tiling; even x-pairs free via ulonglong2, odd via 1 pack

#define KS      15
#define IN_N    4096
#define OUT_N   4084
#define BDX     32
#define BDY     8
#define RX      8
#define RY      2
#define TS_X    (BDX*RX)        // 256
#define TS_Y    (BDY*RY)        // 16
#define SMH     (TS_Y + KS - 1) // 30
#define SMW     (TS_X + KS - 1) // 270
#define SMW_PAD 272
#define NR      (RY + KS - 1)   // 16

typedef unsigned long long u64;

__constant__ u64 cW2[KS * KS];   // (w,w) duplicated pairs
__device__   u64 gW2[KS * KS];   // staging written by prep kernel

__global__ void prep_weights(const float* __restrict__ w)
{
    int i = threadIdx.x;
    if (i < KS * KS) {
        unsigned int b = __float_as_uint(w[i]);
        gW2[i] = ((u64)b << 32) | (u64)b;
    }
}

__device__ __forceinline__ void ffma2(u64& acc, u64 a, u64 b)
{
    asm("fma.rn.f32x2 %0, %1, %2, %0;" : "+l"(acc) : "l"(a), "l"(b));
}
__device__ __forceinline__ u64 pack2(float lo, float hi)
{
    u64 r; asm("mov.b64 %0, {%1, %2};" : "=l"(r) : "f"(lo), "f"(hi)); return r;
}
__device__ __forceinline__ float u64lo(u64 v) { return __uint_as_float((unsigned)v); }
__device__ __forceinline__ float u64hi(u64 v) { return __uint_as_float((unsigned)(v >> 32)); }

// One (i, dy) use: 15 taps x 4 output-pairs, packed weights from constant.
__device__ __forceinline__ void do_use(u64 acc[4], const u64* e, const u64* o, int dy)
{
    const u64* wrow = &cW2[dy * KS];
    #pragma unroll
    for (int dx = 0; dx < KS; ++dx) {
        const u64 wp = wrow[dx];                    // LDCU.64 (uniform, no L1)
        #pragma unroll
        for (int jp = 0; jp < 4; ++jp) {
            const int k = dx + 2 * jp;              // compile-time after unroll
            const u64 xp = (k & 1) ? o[(k - 1) >> 1] : e[k >> 1];
            ffma2(acc[jp], wp, xp);
        }
    }
}

// Build 24-float window as 12 even pairs (free) + 10 odd pairs (1 pack each).
__device__ __forceinline__ void load_window(const float* rowp, u64* e, u64* o)
{
    #pragma unroll
    for (int q = 0; q < 6; ++q) {
        ulonglong2 v = *reinterpret_cast<const ulonglong2*>(rowp + q * 4);
        e[2 * q] = v.x; e[2 * q + 1] = v.y;
    }
    #pragma unroll
    for (int k = 0; k < 10; ++k)
        o[k] = pack2(u64hi(e[k]), u64lo(e[k + 1]));
}

__global__ __launch_bounds__(BDX * BDY)
void conv2d_15x15_f32x2(const float* __restrict__ x,
                        const float* __restrict__ bias,
                        float* __restrict__ out)
{
    __shared__ float sX[SMH][SMW_PAD];

    const int tx  = threadIdx.x;
    const int ty  = threadIdx.y;
    const int tid = ty * BDX + tx;
    const int bx0 = blockIdx.x * TS_X;
    const int by0 = blockIdx.y * TS_Y;

    // ---- stage input halo tile (zero-padded; cols >= SMW zeroed for overread) ----
    for (int idx = tid; idx < SMH * SMW_PAD; idx += BDX * BDY) {
        const int rs = idx / SMW_PAD;
        const int c  = idx % SMW_PAD;
        const int gy = by0 - 1 + rs;
        const int gx = bx0 - 1 + c;
        float v = 0.0f;
        if (c < SMW && gy >= 0 && gy < IN_N && gx >= 0 && gx < IN_N)
            v = x[(size_t)gy * IN_N + gx];
        sX[rs][c] = v;
    }
    __syncthreads();

    u64 acc[RY][4];
    #pragma unroll
    for (int i = 0; i < RY; ++i)
        #pragma unroll
        for (int j = 0; j < 4; ++j)
            acc[i][j] = 0ULL;                        // (0.f, 0.f)

    const int cx = tx * RX;                          // 16B-aligned window base
    const int cy = ty * RY;

    u64 e[12], o[10];

    // ---- diagonal loop: each input row loaded once, serves (i=0,dy=r) & (i=1,dy=r-1) ----
    load_window(&sX[cy][cx], e, o);                  // r = 0
    do_use(acc[0], e, o, 0);

    #pragma unroll 1                                 // keep body in L0 I$
    for (int r = 1; r < NR - 1; ++r) {               // r = 1..14
        load_window(&sX[cy + r][cx], e, o);
        do_use(acc[0], e, o, r);
        do_use(acc[1], e, o, r - 1);
    }

    load_window(&sX[cy + NR - 1][cx], e, o);         // r = 15
    do_use(acc[1], e, o, KS - 1);

    // ---- store: 2 rows x 2 float4, coalesced, guarded ----
    const float b  = bias[0];
    const int   ox = bx0 + cx;
    #pragma unroll
    for (int i = 0; i < RY; ++i) {
        const int oy = by0 + cy + i;
        if (oy < OUT_N) {
            float* rp = out + (size_t)oy * OUT_N;
            float4 s0 = make_float4(u64lo(acc[i][0]) + b, u64hi(acc[i][0]) + b,
                                    u64lo(acc[i][1]) + b, u64hi(acc[i][1]) + b);
            float4 s1 = make_float4(u64lo(acc[i][2]) + b, u64hi(acc[i][2]) + b,
                                    u64lo(acc[i][3]) + b, u64hi(acc[i][3]) + b);
            if (ox < OUT_N)     *reinterpret_cast<float4*>(rp + ox)     = s0;
            if (ox + 4 < OUT_N) *reinterpret_cast<float4*>(rp + ox + 4) = s1;
        }
    }
}

extern "C" void kernel_launch(void* const* d_in, const int* in_sizes, int n_in,
                              void* d_out, int out_size)
{
    const float* x    = (const float*)d_in[0];   // 4096*4096
    const float* w    = (const float*)d_in[1];   // 15*15
    const float* bias = (const float*)d_in[2];   // 1
    float* out        = (float*)d_out;           // 4084*4084

    // 1) duplicate weights into 64-bit (w,w) pairs in __device__ staging
    prep_weights<<<1, 256>>>(w);

    // 2) graph-legal D2D memcpy node: staging -> __constant__ (LDCU path)
    void* gp = nullptr;
    cudaGetSymbolAddress(&gp, gW2);
    cudaMemcpyToSymbolAsync(cW2, gp, KS * KS * sizeof(u64), 0,
                            cudaMemcpyDeviceToDevice, 0);

    // 3) main kernel
    dim3 block(BDX, BDY);
    dim3 grid((OUT_N + TS_X - 1) / TS_X,          // 16
              (OUT_N + TS_Y - 1) / TS_Y);         // 256
    conv2d_15x15_f32x2<<<grid, block>>>(x, bias, out);
}

// round 5
// speedup vs baseline: 1.1944x; 1.0305x over previous
#include <cuda_runtime.h>

// Conv2D 4096x4096, 15x15, pad=1 -> 4084x4084, + bias.
// R5: FFMA2 (fma.rn.f32x2) + RY=4 diagonal row-reuse (LDS.128/output: 6 -> 3.4),
//     div-free staging with interior fast path, incremental weight-row pointer,
//     bias folded into accumulator init.

#define KS      15
#define IN_N    4096
#define OUT_N   4084
#define BDX     32
#define BDY     8
#define RX      8
#define RY      4
#define TS_X    (BDX*RX)        // 256
#define TS_Y    (BDY*RY)        // 32
#define SMH     (TS_Y + KS - 1) // 46
#define SMW     (TS_X + KS - 1) // 270
#define SMW_PAD 272
#define NR      (RY + KS - 1)   // 18 distinct input rows per thread

typedef unsigned long long u64;

__constant__ u64 cW2[KS * KS];   // duplicated (w,w) weight pairs
__device__   u64 gW2[KS * KS];   // staging, written by prep kernel

__global__ void prep_weights(const float* __restrict__ w)
{
    int i = threadIdx.x;
    if (i < KS * KS) {
        unsigned int b = __float_as_uint(w[i]);
        gW2[i] = ((u64)b << 32) | (u64)b;
    }
}

__device__ __forceinline__ void ffma2(u64& acc, u64 a, u64 b)
{
    asm("fma.rn.f32x2 %0, %1, %2, %0;" : "+l"(acc) : "l"(a), "l"(b));
}
__device__ __forceinline__ u64 pack2(float lo, float hi)
{
    u64 r; asm("mov.b64 %0, {%1, %2};" : "=l"(r) : "f"(lo), "f"(hi)); return r;
}
__device__ __forceinline__ float u64lo(u64 v) { return __uint_as_float((unsigned)v); }
__device__ __forceinline__ float u64hi(u64 v) { return __uint_as_float((unsigned)(v >> 32)); }

// One (acc-row, dy) application: 15 taps x 4 output pairs.
// wrow = &cW2[dy*KS] passed as pointer -> LDC.64 with immediate offsets.
__device__ __forceinline__ void do_use(u64 acc[4], const u64* e, const u64* o,
                                       const u64* wrow)
{
    #pragma unroll
    for (int dx = 0; dx < KS; ++dx) {
        const u64 wp = wrow[dx];                    // LDC.64, imm offset
        #pragma unroll
        for (int jp = 0; jp < 4; ++jp) {
            const int k = dx + 2 * jp;              // compile-time
            const u64 xp = (k & 1) ? o[(k - 1) >> 1] : e[k >> 1];
            ffma2(acc[jp], wp, xp);
        }
    }
}

// 24-float window: 12 even pairs via LDS.128, 10 odd pairs via 1 pack each.
__device__ __forceinline__ void load_window(const float* rowp, u64* e, u64* o)
{
    #pragma unroll
    for (int q = 0; q < 6; ++q) {
        ulonglong2 v = *reinterpret_cast<const ulonglong2*>(rowp + q * 4);
        e[2 * q] = v.x; e[2 * q + 1] = v.y;
    }
    #pragma unroll
    for (int k = 0; k < 10; ++k)
        o[k] = pack2(u64hi(e[k]), u64lo(e[k + 1]));
}

__global__ __launch_bounds__(BDX * BDY, 2)
void conv2d_15x15_f32x2(const float* __restrict__ x,
                        const float* __restrict__ bias,
                        float* __restrict__ out)
{
    __shared__ float sX[SMH][SMW_PAD];

    const int lane = threadIdx.x;
    const int wid  = threadIdx.y;                    // warp id (BDX == 32)
    const int bx0  = blockIdx.x * TS_X;
    const int by0  = blockIdx.y * TS_Y;

    // ---- stage input halo tile (div-free; interior blocks skip all guards) ----
    const bool interior = (by0 >= 1) && (by0 + SMH - 1 <= IN_N) &&
                          (bx0 >= 1) && (bx0 + SMW_PAD - 1 <= IN_N);
    if (interior) {
        const float* base = x + (size_t)(by0 - 1) * IN_N + (bx0 - 1);
        for (int r = wid; r < SMH; r += BDY) {
            const float* rowp = base + (size_t)r * IN_N;
            #pragma unroll
            for (int k = 0; k < 9; ++k) {            // 272 = 8*32 + 16
                const int c = lane + 32 * k;
                if (c < SMW_PAD) sX[r][c] = rowp[c];
            }
        }
    } else {
        for (int r = wid; r < SMH; r += BDY) {
            const int gy = by0 - 1 + r;
            const bool rok = (gy >= 0) && (gy < IN_N);
            #pragma unroll
            for (int k = 0; k < 9; ++k) {
                const int c = lane + 32 * k;
                if (c < SMW_PAD) {
                    const int gx = bx0 - 1 + c;
                    float v = 0.0f;
                    if (rok && gx >= 0 && gx < IN_N)
                        v = x[(size_t)gy * IN_N + gx];
                    sX[r][c] = v;
                }
            }
        }
    }
    __syncthreads();

    // ---- accumulators seeded with bias (fma chain starts at b) ----
    const float bval = bias[0];
    const u64 bpair = pack2(bval, bval);
    u64 acc[RY][4];
    #pragma unroll
    for (int i = 0; i < RY; ++i)
        #pragma unroll
        for (int j = 0; j < 4; ++j)
            acc[i][j] = bpair;

    const int cx = lane * RX;                        // 16B-aligned window base
    const int cy = wid * RY;

    u64 e[12], o[10];

    // ---- diagonal loop: each of 18 rows loaded once, serves up to 4 acc rows ----
    // prologue r = 0..2
    load_window(&sX[cy + 0][cx], e, o);
    do_use(acc[0], e, o, &cW2[0]);
    load_window(&sX[cy + 1][cx], e, o);
    do_use(acc[0], e, o, &cW2[1 * KS]);
    do_use(acc[1], e, o, &cW2[0]);
    load_window(&sX[cy + 2][cx], e, o);
    do_use(acc[0], e, o, &cW2[2 * KS]);
    do_use(acc[1], e, o, &cW2[1 * KS]);
    do_use(acc[2], e, o, &cW2[0]);

    // steady r = 3..14: all 4 acc rows active; weight ptr strides by KS
    {
        const u64* wr = &cW2[3 * KS];
        #pragma unroll 1
        for (int r = 3; r <= 14; ++r, wr += KS) {
            load_window(&sX[cy + r][cx], e, o);
            do_use(acc[0], e, o, wr);
            do_use(acc[1], e, o, wr - KS);
            do_use(acc[2], e, o, wr - 2 * KS);
            do_use(acc[3], e, o, wr - 3 * KS);
        }
    }

    // epilogue r = 15..17
    load_window(&sX[cy + 15][cx], e, o);
    do_use(acc[1], e, o, &cW2[14 * KS]);
    do_use(acc[2], e, o, &cW2[13 * KS]);
    do_use(acc[3], e, o, &cW2[12 * KS]);
    load_window(&sX[cy + 16][cx], e, o);
    do_use(acc[2], e, o, &cW2[14 * KS]);
    do_use(acc[3], e, o, &cW2[13 * KS]);
    load_window(&sX[cy + 17][cx], e, o);
    do_use(acc[3], e, o, &cW2[14 * KS]);

    // ---- store: 4 rows x 2 float4, coalesced, guarded ----
    const int ox = bx0 + cx;
    #pragma unroll
    for (int i = 0; i < RY; ++i) {
        const int oy = by0 + cy + i;
        if (oy < OUT_N) {
            float* rp = out + (size_t)oy * OUT_N;
            float4 s0 = make_float4(u64lo(acc[i][0]), u64hi(acc[i][0]),
                                    u64lo(acc[i][1]), u64hi(acc[i][1]));
            float4 s1 = make_float4(u64lo(acc[i][2]), u64hi(acc[i][2]),
                                    u64lo(acc[i][3]), u64hi(acc[i][3]));
            if (ox < OUT_N)     *reinterpret_cast<float4*>(rp + ox)     = s0;
            if (ox + 4 < OUT_N) *reinterpret_cast<float4*>(rp + ox + 4) = s1;
        }
    }
}

extern "C" void kernel_launch(void* const* d_in, const int* in_sizes, int n_in,
                              void* d_out, int out_size)
{
    const float* x    = (const float*)d_in[0];   // 4096*4096
    const float* w    = (const float*)d_in[1];   // 15*15
    const float* bias = (const float*)d_in[2];   // 1
    float* out        = (float*)d_out;           // 4084*4084

    prep_weights<<<1, 256>>>(w);

    void* gp = nullptr;
    cudaGetSymbolAddress(&gp, gW2);
    cudaMemcpyToSymbolAsync(cW2, gp, KS * KS * sizeof(u64), 0,
                            cudaMemcpyDeviceToDevice, 0);

    dim3 block(BDX, BDY);
    dim3 grid((OUT_N + TS_X - 1) / TS_X,          // 16
              (OUT_N + TS_Y - 1) / TS_Y);         // 128
    conv2d_15x15_f32x2<<<grid, block>>>(x, bias, out);
}

// round 7
// speedup vs baseline: 2.0603x; 1.7250x over previous
#include <cuda_runtime.h>
#include <cuda_fp16.h>
#include <cstdint>

// Conv2D 4096x4096, 15x15, pad=1 -> 4084x4084, + bias.
// R7: warp-level tensor cores (mma.sync.m16n8k16 f16, fp32 accum).
// D[y,x] = sum_dy A_dy @ B_dy^T: A_dy = row-shifted fp16 input windows
// (ldmatrix, shift = +dy rows), B_dy = Toeplitz band of weight row dy,
// precomputed in exact B-fragment lane layout by a prep kernel.

#define KS      15
#define IN_N    4096
#define OUT_N   4084
#define CTA_Y   128            // 4 warps in y * 32
#define CTA_X   64             // 2 warps in x * 32
#define AROWS   142            // 128 + 14 halo
#define ACOLS   80             // 64 + 14 halo + 2 pad (cols 78,79 zero-filled)
#define ASTRIDE 88             // fp16 elems per row; 176B = 48 mod 128 -> conflict-free
#define NDY     KS
#define NFRAG   4              // B fragments per dy (d = 2h - s + 1)

__device__ uint2 gBf[NDY * NFRAG * 32];   // B fragments, lane-layout, (b0,b1)

// t = 8*(d-1) + kl - nl ; b0: kl = 2*tg(+1), b1: kl = 2*tg+8(+1); nl = gp
__global__ void prep_Bfrag(const float* __restrict__ w)
{
    int idx = blockIdx.x * blockDim.x + threadIdx.x;     // [0, 15*4*32)
    if (idx >= NDY * NFRAG * 32) return;
    const int lane = idx & 31;
    const int d    = (idx >> 5) & 3;
    const int dy   = idx >> 7;
    const int tg   = lane & 3;
    const int gp   = lane >> 2;
    const int base = 8 * (d - 1) - gp;
    float v[4];
    #pragma unroll
    for (int q = 0; q < 4; ++q) {
        const int kl = 2 * tg + (q & 1) + 8 * (q >> 1);
        const int t  = base + kl;
        v[q] = (t >= 0 && t < KS) ? w[dy * KS + t] : 0.0f;
    }
    __half2 lo = __floats2half2_rn(v[0], v[1]);
    __half2 hi = __floats2half2_rn(v[2], v[3]);
    uint2 r;
    r.x = *reinterpret_cast<uint32_t*>(&lo);
    r.y = *reinterpret_cast<uint32_t*>(&hi);
    gBf[idx] = r;
}

__device__ __forceinline__ uint32_t smem_u32(const void* p)
{
    uint32_t a;
    asm("{ .reg .u64 t; cvta.to.shared.u64 t, %1; cvt.u32.u64 %0, t; }"
        : "=r"(a) : "l"(p));
    return a;
}
__device__ __forceinline__ void ldmA(uint32_t a[4], uint32_t addr)
{
    asm volatile("ldmatrix.sync.aligned.m8n8.x4.shared.b16 {%0,%1,%2,%3}, [%4];"
                 : "=r"(a[0]), "=r"(a[1]), "=r"(a[2]), "=r"(a[3]) : "r"(addr));
}
__device__ __forceinline__ void mma16816(float c[4], const uint32_t a[4],
                                         uint32_t b0, uint32_t b1)
{
    asm volatile(
        "mma.sync.aligned.m16n8k16.row.col.f32.f16.f16.f32 "
        "{%0,%1,%2,%3}, {%4,%5,%6,%7}, {%8,%9}, {%0,%1,%2,%3};"
        : "+f"(c[0]), "+f"(c[1]), "+f"(c[2]), "+f"(c[3])
        : "r"(a[0]), "r"(a[1]), "r"(a[2]), "r"(a[3]), "r"(b0), "r"(b1));
}

__global__ __launch_bounds__(256)
void conv2d_mma_kernel(const float* __restrict__ x,
                       const float* __restrict__ bias,
                       float* __restrict__ out)
{
    __shared__ __align__(32) __half sA[AROWS * ASTRIDE];   // 24992 B
    __shared__ uint2 sBf[NDY * NFRAG * 32];                // 15360 B

    const int tid  = threadIdx.x;
    const int lane = tid & 31;
    const int wid  = tid >> 5;
    const int wy   = wid >> 1;          // 0..3
    const int wx   = wid & 1;           // 0..1
    const int X0   = blockIdx.x * CTA_X;
    const int Y0   = blockIdx.y * CTA_Y;

    // ---- stage B fragments (global -> shared) ----
    for (int i = tid; i < NDY * NFRAG * 32; i += 256)
        sBf[i] = gBf[i];

    // ---- stage A: 142 rows x 80 cols fp32 -> fp16 (smem col j <-> input col X0-1+j)
    for (int idx = tid; idx < AROWS * (ACOLS / 2); idx += 256) {
        const int r  = idx / (ACOLS / 2);
        const int p  = idx - r * (ACOLS / 2);
        const int gy = Y0 - 1 + r;
        const int gx = X0 - 1 + 2 * p;
        float v0 = 0.0f, v1 = 0.0f;
        if ((unsigned)gy < IN_N) {
            const float* rp = x + (size_t)gy * IN_N;
            if ((unsigned)gx       < IN_N) v0 = rp[gx];
            if ((unsigned)(gx + 1) < IN_N) v1 = rp[gx + 1];
        }
        __half2 h = __floats2half2_rn(v0, v1);
        *reinterpret_cast<__half2*>(&sA[r * ASTRIDE + 2 * p]) = h;
    }
    __syncthreads();

    // ---- accumulators seeded with bias: acc[mh][2*qp+s][4] ----
    const float bval = bias[0];
    float acc[2][4][4];
    #pragma unroll
    for (int m = 0; m < 2; ++m)
        #pragma unroll
        for (int j = 0; j < 4; ++j)
            #pragma unroll
            for (int e = 0; e < 4; ++e)
                acc[m][j][e] = bval;

    // per-thread ldmatrix address part: row (lane&15), k-half (lane>>4)*16B
    const uint32_t sA_b = smem_u32(sA);
    const uint32_t lanepart = sA_b + (uint32_t)((lane & 15) * (ASTRIDE * 2))
                            + (uint32_t)(64 * wx) + (uint32_t)((lane >> 4) << 4);
    const uint32_t sBf_b = smem_u32(sBf);
    const int rowbase = 32 * wy;        // warp's first output row (local)

    #pragma unroll 1
    for (int dy = 0; dy < NDY; ++dy) {
        // 4 B fragments for this dy
        uint32_t b[NFRAG][2];
        #pragma unroll
        for (int d = 0; d < NFRAG; ++d) {
            uint32_t addr = sBf_b + (uint32_t)(((dy * NFRAG + d) * 32 + lane) * 8);
            asm volatile("ld.shared.v2.u32 {%0,%1}, [%2];"
                         : "=r"(b[d][0]), "=r"(b[d][1]) : "r"(addr));
        }
        #pragma unroll
        for (int mh = 0; mh < 2; ++mh) {
            const uint32_t rbase = lanepart
                + (uint32_t)((rowbase + 16 * mh + dy) * (ASTRIDE * 2));
            uint32_t a[3][4];
            ldmA(a[0], rbase);
            ldmA(a[1], rbase + 32);
            ldmA(a[2], rbase + 64);
            #pragma unroll
            for (int qp = 0; qp < 2; ++qp)
                #pragma unroll
                for (int s = 0; s < 2; ++s) {
                    float* c = acc[mh][2 * qp + s];
                    mma16816(c, a[qp],     b[1 - s][0], b[1 - s][1]);   // h=0
                    mma16816(c, a[qp + 1], b[3 - s][0], b[3 - s][1]);   // h=1
                }
        }
    }

    // ---- epilogue: D frag -> gmem (float2 stores) ----
    const int tg = lane & 3;
    const int gp = lane >> 2;
    #pragma unroll
    for (int mh = 0; mh < 2; ++mh)
        #pragma unroll
        for (int j = 0; j < 4; ++j) {
            const int col = X0 + 32 * wx + 8 * j + 2 * tg;
            const int r0  = Y0 + 32 * wy + 16 * mh + gp;
            if (col < OUT_N) {
                if (r0 < OUT_N) {
                    float2 v = make_float2(acc[mh][j][0], acc[mh][j][1]);
                    *reinterpret_cast<float2*>(&out[(size_t)r0 * OUT_N + col]) = v;
                }
                if (r0 + 8 < OUT_N) {
                    float2 v = make_float2(acc[mh][j][2], acc[mh][j][3]);
                    *reinterpret_cast<float2*>(&out[(size_t)(r0 + 8) * OUT_N + col]) = v;
                }
            }
        }
}

extern "C" void kernel_launch(void* const* d_in, const int* in_sizes, int n_in,
                              void* d_out, int out_size)
{
    const float* x    = (const float*)d_in[0];   // 4096*4096
    const float* w    = (const float*)d_in[1];   // 15*15
    const float* bias = (const float*)d_in[2];   // 1
    float* out        = (float*)d_out;           // 4084*4084

    prep_Bfrag<<<(NDY * NFRAG * 32 + 255) / 256, 256>>>(w);

    dim3 grid((OUT_N + CTA_X - 1) / CTA_X,       // 64
              (OUT_N + CTA_Y - 1) / CTA_Y);      // 32
    conv2d_mma_kernel<<<grid, 256>>>(x, bias, out);
}